// round 7
// baseline (speedup 1.0000x reference)
#include <cuda_runtime.h>
#include <cuda_bf16.h>

#define BETA   0.001f
#define TPB    256
#define SPB    4        // segments per block (2 warps each)
#define MAXB   2048
#define LOG2E  1.4426950408889634f
#define LN2    0.6931471805599453f

__device__ float    g_part[MAXB];
__device__ unsigned g_done = 0;

__device__ __forceinline__ float ex2f(float x){ float r; asm("ex2.approx.f32 %0,%1;":"=f"(r):"f"(x)); return r; }
__device__ __forceinline__ float lg2f(float x){ float r; asm("lg2.approx.f32 %0,%1;":"=f"(r):"f"(x)); return r; }

// One 32x32 dense chunk-block: lane j (exp e) vs 32 i's from shared (zero-padded).
// prod(1 + e*b_i), lg2 every 8 factors (pa: even, pb: odd). Factor <= ~2^14,
// 4 per half-chain -> pa*pb <= 2^112, no overflow. e==0 (invalid j) -> 0.
__device__ __forceinline__ float sweep1(const float* __restrict__ b, float e) {
    float acc = 0.0f;
    #pragma unroll
    for (int blk = 0; blk < 4; ++blk) {
        float4 v0 = *(const float4*)(b + blk * 8);
        float4 v1 = *(const float4*)(b + blk * 8 + 4);
        float pa = fmaf(e, v0.x, 1.0f);
        float pb = fmaf(e, v0.y, 1.0f);
        float t;
        t = e * v0.z; pa = fmaf(pa, t, pa);
        t = e * v0.w; pb = fmaf(pb, t, pb);
        t = e * v1.x; pa = fmaf(pa, t, pa);
        t = e * v1.y; pb = fmaf(pb, t, pb);
        t = e * v1.z; pa = fmaf(pa, t, pa);
        t = e * v1.w; pb = fmaf(pb, t, pb);
        acc += lg2f(pa * pb);
    }
    return acc;
}

// Two chains sharing the same b-chunk loads (both results added to acc).
__device__ __forceinline__ void sweep2(const float* __restrict__ b,
                                       float e0, float e1, float& acc) {
    #pragma unroll
    for (int blk = 0; blk < 4; ++blk) {
        float4 v0 = *(const float4*)(b + blk * 8);
        float4 v1 = *(const float4*)(b + blk * 8 + 4);
        float pa0 = fmaf(e0, v0.x, 1.0f), pb0 = fmaf(e0, v0.y, 1.0f);
        float pa1 = fmaf(e1, v0.x, 1.0f), pb1 = fmaf(e1, v0.y, 1.0f);
        float t;
        t = e0 * v0.z; pa0 = fmaf(pa0, t, pa0);
        t = e1 * v0.z; pa1 = fmaf(pa1, t, pa1);
        t = e0 * v0.w; pb0 = fmaf(pb0, t, pb0);
        t = e1 * v0.w; pb1 = fmaf(pb1, t, pb1);
        t = e0 * v1.x; pa0 = fmaf(pa0, t, pa0);
        t = e1 * v1.x; pa1 = fmaf(pa1, t, pa1);
        t = e0 * v1.y; pb0 = fmaf(pb0, t, pb0);
        t = e1 * v1.y; pb1 = fmaf(pb1, t, pb1);
        t = e0 * v1.z; pa0 = fmaf(pa0, t, pa0);
        t = e1 * v1.z; pa1 = fmaf(pa1, t, pa1);
        t = e0 * v1.w; pb0 = fmaf(pb0, t, pb0);
        t = e1 * v1.w; pb1 = fmaf(pb1, t, pb1);
        acc += lg2f(pa0 * pb0);
        acc += lg2f(pa1 * pb1);
    }
}

__global__ void __launch_bounds__(TPB) rm_kernel(
    const float* __restrict__ logits,
    const void*  __restrict__ cu_raw,
    int n_seg,
    float* __restrict__ out)
{
    __shared__ __align__(16) float em[SPB][128];   // e^{-x}, zero-padded
    __shared__ __align__(16) float ep[SPB][128];   // e^{+x}, zero-padded
    __shared__ float partv[SPB][2];
    __shared__ float ws[TPB / 32];
    __shared__ bool  isLast;

    const int tid  = threadIdx.x;
    const int w    = tid >> 5;
    const int lane = tid & 31;
    const int segl = w >> 1;
    const int sub  = w & 1;
    const int s    = blockIdx.x * SPB + segl;
    const bool segv = (s < n_seg);

    int L = 2, C = 0;
    const float* gx = logits;
    if (segv) {
        const int* cu32 = (const int*)cu_raw;
        long long a, bnd;
        if (cu32[1] == 0) {                     // int64 layout (cu[0]=0)
            const long long* cu64 = (const long long*)cu_raw;
            a = cu64[s]; bnd = cu64[s + 1];
        } else {
            a = (long long)cu32[s]; bnd = (long long)cu32[s + 1];
        }
        L = (int)(bnd - a);
        C = (L + 31) >> 5;
        gx = logits + a;
    }

    // Stage: warp `sub` covers chunks {2*sub, 2*sub+1}. sq/wsum partials are
    // linear -> fold per warp, combine at block level.
    float sq = 0.0f, wsum = 0.0f;
    if (segv) {
        #pragma unroll
        for (int rr = 0; rr < 2; ++rr) {
            int r = sub * 2 + rr;
            int j = (r << 5) + lane;
            bool valid = (j < L);
            float xv = valid ? gx[j] : 0.0f;
            sq += xv * xv;
            int nv = L - (r << 5); nv = (nv > 32) ? 32 : nv;
            if (valid) wsum += xv * (float)(2 * lane - (nv - 1));
            float xl = xv * LOG2E;
            ep[segl][j] = valid ? ex2f(xl)  : 0.0f;
            em[segl][j] = valid ? ex2f(-xl) : 0.0f;
        }
    }
    __syncthreads();

    // Straight-line sweep schedule per (C, sub). sub0: diagonals (+cross(0,1)
    // at C=4); sub1: crosses. Balanced: 1/0, 2/1, 3/3, 5/5 sweeps.
    float acc = 0.0f, accd = 0.0f;
    if (segv) {
        const float* base = em[segl];
        const float* epb  = ep[segl];
        if (sub == 0) {
            float e0 = epb[lane];
            accd += sweep1(base, e0);
            if (C >= 2) {
                float e1 = epb[32 + lane];
                accd += sweep1(base + 32, e1);
                if (C >= 3) {
                    float e2 = epb[64 + lane];
                    accd += sweep1(base + 64, e2);
                    if (C >= 4) {
                        float e3 = epb[96 + lane];
                        accd += sweep1(base + 96, e3);
                        acc  += sweep1(base, e1);        // cross (0,1)
                    }
                }
            }
        } else {
            if (C >= 2) {
                float e1 = epb[32 + lane];
                if (C == 2) {
                    acc += sweep1(base, e1);             // (0,1)
                } else if (C == 3) {
                    float e2 = epb[64 + lane];
                    sweep2(base, e1, e2, acc);           // (0,1),(0,2)
                    acc += sweep1(base + 32, e2);        // (1,2)
                } else {
                    float e2 = epb[64 + lane];
                    float e3 = epb[96 + lane];
                    sweep2(base,      e2, e3, acc);      // (0,2),(0,3)
                    sweep2(base + 32, e2, e3, acc);      // (1,2),(1,3)
                    acc += sweep1(base + 64, e3);        // (2,3)
                }
            }
        }
    }

    // Fold per-segment uniform coefficients before the warp reduction.
    float v = 0.0f;
    if (segv) {
        float invP = 2.0f / ((float)L * (float)(L - 1));
        v = (acc + 0.5f * accd) * (LN2 * invP)
          + wsum * (0.5f * invP)
          + sq   * (BETA / (float)L);
    }
    #pragma unroll
    for (int o = 16; o > 0; o >>= 1)
        v += __shfl_xor_sync(0xffffffffu, v, o);
    if (lane == 0) {
        if (segv && sub == 0) v -= LN2 / (float)(L - 1);   // diag constant, once
        partv[segl][sub] = v;
    }
    __syncthreads();

    if (tid == 0) {
        float p = 0.0f;
        #pragma unroll
        for (int k = 0; k < SPB; ++k) p += partv[k][0] + partv[k][1];
        g_part[blockIdx.x] = p;
        __threadfence();
        unsigned d = atomicAdd(&g_done, 1u);
        isLast = (d == gridDim.x - 1);
    }
    __syncthreads();

    if (isLast) {
        float t = 0.0f;
        for (int k = tid; k < (int)gridDim.x; k += TPB) t += g_part[k];  // fixed order
        #pragma unroll
        for (int o = 16; o > 0; o >>= 1) t += __shfl_xor_sync(0xffffffffu, t, o);
        if (lane == 0) ws[w] = t;
        __syncthreads();
        if (w == 0) {
            t = (lane < TPB / 32) ? ws[lane] : 0.0f;
            #pragma unroll
            for (int o = 4; o > 0; o >>= 1) t += __shfl_xor_sync(0xffffffffu, t, o);
            if (lane == 0) {
                out[0] = t / (float)n_seg;
                g_done = 0;   // reset for next graph replay
            }
        }
    }
}

extern "C" void kernel_launch(void* const* d_in, const int* in_sizes, int n_in,
                              void* d_out, int out_size) {
    const float* logits = (const float*)d_in[0];
    const void*  cu     = (const void*)d_in[1];
    int n_seg  = in_sizes[1] - 1;
    int blocks = (n_seg + SPB - 1) / SPB;
    if (blocks > MAXB) blocks = MAXB;

    rm_kernel<<<blocks, TPB>>>(logits, cu, n_seg, (float*)d_out);
}

// round 8
// speedup vs baseline: 1.2209x; 1.2209x over previous
#include <cuda_runtime.h>
#include <cuda_bf16.h>

#define BETA   0.001f
#define TPB    256
#define SPB    4        // segments per block (2 warps each)
#define MAXB   2048
#define LOG2E  1.4426950408889634f
#define LN2    0.6931471805599453f

typedef unsigned long long u64;

__device__ float    g_part[MAXB];
__device__ unsigned g_done = 0;

__device__ __forceinline__ float ex2f(float x){ float r; asm("ex2.approx.f32 %0,%1;":"=f"(r):"f"(x)); return r; }
__device__ __forceinline__ float lg2f(float x){ float r; asm("lg2.approx.f32 %0,%1;":"=f"(r):"f"(x)); return r; }

__device__ __forceinline__ u64 pack2(float x, float y){ u64 r; asm("mov.b64 %0,{%1,%2};":"=l"(r):"f"(x),"f"(y)); return r; }
__device__ __forceinline__ void unpack2(u64 v, float& x, float& y){ asm("mov.b64 {%0,%1},%2;":"=f"(x),"=f"(y):"l"(v)); }
__device__ __forceinline__ u64 fma2(u64 a, u64 b, u64 c){ u64 r; asm("fma.rn.f32x2 %0,%1,%2,%3;":"=l"(r):"l"(a),"l"(b),"l"(c)); return r; }
__device__ __forceinline__ u64 mul2(u64 a, u64 b){ u64 r; asm("mul.rn.f32x2 %0,%1,%2;":"=l"(r):"l"(a),"l"(b)); return r; }

// i-chunk at b[0..31] (shared, zero-padded) against NJ j-chunk chains.
// Chain j accumulates prod(1 + e[j]*b_i) in packed f32x2 (lo: even i, hi: odd i);
// lg2 taken every 8 factors. Factor <= ~2^14, 4 per packed half -> product <= 2^112.
// Chain 0 is the DIAGONAL chunk (rj==ri): its sum goes to accd (weight 1/2 later).
template<int NJ>
__device__ __forceinline__ void sweepN(const float* __restrict__ b,
                                       const float* __restrict__ e,
                                       float& acc, float& accd)
{
    u64 E[NJ];
    #pragma unroll
    for (int j = 0; j < NJ; ++j) E[j] = pack2(e[j], e[j]);

    float r[NJ];
    #pragma unroll
    for (int j = 0; j < NJ; ++j) r[j] = 0.0f;

    #pragma unroll
    for (int blk = 0; blk < 4; ++blk) {
        float4 v0 = *(const float4*)(b + blk * 8);
        float4 v1 = *(const float4*)(b + blk * 8 + 4);
        u64 B0 = pack2(v0.x, v0.y);
        u64 B1 = pack2(v0.z, v0.w);
        u64 B2 = pack2(v1.x, v1.y);
        u64 B3 = pack2(v1.z, v1.w);
        #pragma unroll
        for (int j = 0; j < NJ; ++j) {
            u64 P = mul2(E[j], B0);          // t0 (then P = 1*(1+t) pattern below)
            u64 one = pack2(1.0f, 1.0f);
            P = fma2(one, P, one);           // P = 1 + t0
            u64 t;
            t = mul2(E[j], B1); P = fma2(P, t, P);
            t = mul2(E[j], B2); P = fma2(P, t, P);
            t = mul2(E[j], B3); P = fma2(P, t, P);
            float pa, pb; unpack2(P, pa, pb);
            r[j] += lg2f(pa * pb);
        }
    }
    accd += r[0];
    #pragma unroll
    for (int j = 1; j < NJ; ++j) acc += r[j];
}

__global__ void __launch_bounds__(TPB, 5) rm_kernel(
    const float* __restrict__ logits,
    const void*  __restrict__ cu_raw,
    int n_seg,
    float* __restrict__ out)
{
    __shared__ __align__(16) float em[SPB][128];   // e^{-x}, zero-padded
    __shared__ __align__(16) float ep[SPB][128];   // e^{+x}, zero-padded
    __shared__ float partv[SPB][2];
    __shared__ float ws[TPB / 32];
    __shared__ bool  isLast;

    const int tid  = threadIdx.x;
    const int w    = tid >> 5;
    const int lane = tid & 31;
    const int segl = w >> 1;
    const int sub  = w & 1;
    const int s    = blockIdx.x * SPB + segl;
    const bool segv = (s < n_seg);

    int L = 2, C = 0;
    const float* gx = logits;
    if (segv) {
        const int* cu32 = (const int*)cu_raw;
        long long a, bnd;
        if (cu32[1] == 0) {                     // int64 layout (cu[0]=0)
            const long long* cu64 = (const long long*)cu_raw;
            a = cu64[s]; bnd = cu64[s + 1];
        } else {
            a = (long long)cu32[s]; bnd = (long long)cu32[s + 1];
        }
        L = (int)(bnd - a);
        C = (L + 31) >> 5;
        gx = logits + a;
    }

    // Stage: warp `sub` covers chunks {2*sub, 2*sub+1}; sq/wsum partials fold later.
    float sq = 0.0f, wsum = 0.0f;
    if (segv) {
        #pragma unroll
        for (int rr = 0; rr < 2; ++rr) {
            int r = sub * 2 + rr;
            int j = (r << 5) + lane;
            bool valid = (j < L);
            float xv = valid ? gx[j] : 0.0f;
            sq += xv * xv;
            int nv = L - (r << 5); nv = (nv > 32) ? 32 : nv;
            if (valid) wsum += xv * (float)(2 * lane - (nv - 1));
            float xl = xv * LOG2E;
            ep[segl][j] = valid ? ex2f(xl)  : 0.0f;
            em[segl][j] = valid ? ex2f(-xl) : 0.0f;
        }
    }
    __syncthreads();

    // ri-parity split: sub0 sweeps from i-chunks {0,2}, sub1 from {1,3}.
    // Chain 0 of each sweep is the diagonal (rj==ri); chains 1.. are rj>ri.
    float acc = 0.0f, accd = 0.0f;
    if (segv) {
        const float* base = em[segl];
        float e[4];
        #pragma unroll
        for (int r = 0; r < 4; ++r) e[r] = ep[segl][(r << 5) + lane];

        if (sub == 0) {
            switch (C) {
                case 1:  sweepN<1>(base, e, acc, accd); break;
                case 2:  sweepN<2>(base, e, acc, accd); break;
                case 3:  sweepN<3>(base, e, acc, accd);
                         sweepN<1>(base + 64, e + 2, acc, accd); break;
                default: sweepN<4>(base, e, acc, accd);
                         sweepN<2>(base + 64, e + 2, acc, accd); break;
            }
        } else {
            switch (C) {
                case 1:  break;
                case 2:  sweepN<1>(base + 32, e + 1, acc, accd); break;
                case 3:  sweepN<2>(base + 32, e + 1, acc, accd); break;
                default: sweepN<3>(base + 32, e + 1, acc, accd);
                         sweepN<1>(base + 96, e + 3, acc, accd); break;
            }
        }
    }

    // Fold per-segment uniform coefficients before the warp reduction.
    float v = 0.0f;
    if (segv) {
        float invP = 2.0f / ((float)L * (float)(L - 1));
        v = (acc + 0.5f * accd) * (LN2 * invP)
          + wsum * (0.5f * invP)
          + sq   * (BETA / (float)L);
    }
    #pragma unroll
    for (int o = 16; o > 0; o >>= 1)
        v += __shfl_xor_sync(0xffffffffu, v, o);
    if (lane == 0) {
        if (segv && sub == 0) v -= LN2 / (float)(L - 1);   // diag constant, once
        partv[segl][sub] = v;
    }
    __syncthreads();

    if (tid == 0) {
        float p = 0.0f;
        #pragma unroll
        for (int k = 0; k < SPB; ++k) p += partv[k][0] + partv[k][1];
        g_part[blockIdx.x] = p;
        __threadfence();
        unsigned d = atomicAdd(&g_done, 1u);
        isLast = (d == gridDim.x - 1);
    }
    __syncthreads();

    if (isLast) {
        float t = 0.0f;
        for (int k = tid; k < (int)gridDim.x; k += TPB) t += g_part[k];  // fixed order
        #pragma unroll
        for (int o = 16; o > 0; o >>= 1) t += __shfl_xor_sync(0xffffffffu, t, o);
        if (lane == 0) ws[w] = t;
        __syncthreads();
        if (w == 0) {
            t = (lane < TPB / 32) ? ws[lane] : 0.0f;
            #pragma unroll
            for (int o = 4; o > 0; o >>= 1) t += __shfl_xor_sync(0xffffffffu, t, o);
            if (lane == 0) {
                out[0] = t / (float)n_seg;
                g_done = 0;   // reset for next graph replay
            }
        }
    }
}

extern "C" void kernel_launch(void* const* d_in, const int* in_sizes, int n_in,
                              void* d_out, int out_size) {
    const float* logits = (const float*)d_in[0];
    const void*  cu     = (const void*)d_in[1];
    int n_seg  = in_sizes[1] - 1;
    int blocks = (n_seg + SPB - 1) / SPB;
    if (blocks > MAXB) blocks = MAXB;

    rm_kernel<<<blocks, TPB>>>(logits, cu, n_seg, (float*)d_out);
}